// round 6
// baseline (speedup 1.0000x reference)
#include <cuda_runtime.h>

#define F_IN   512
#define H_DIM  16
#define C_OUT  7
#define NMAX   100000
#define EMAX   3200000
#define TOTMAX (NMAX + EMAX)
#define CHUNK  512
#define NCMAX  ((NMAX + CHUNK - 1) / CHUNK)

// -------- scratch (static device globals; no runtime allocation) --------
static __device__ float g_h0[NMAX * H_DIM];
static __device__ float g_h1[NMAX * H_DIM];
static __device__ int   g_counts[NMAX];
static __device__ int   g_cursor[NMAX];
static __device__ int   g_off[NMAX + 1];
static __device__ int   g_csr[TOTMAX];
static __device__ int   g_csums[NCMAX];

// packed f32x2 FMA: d = a*b + d (two fp32 lanes per instruction; PTX-only form)
__device__ __forceinline__ void fma2(unsigned long long& d,
                                     unsigned long long a, unsigned long long b)
{
    asm("fma.rn.f32x2 %0, %1, %2, %0;" : "+l"(d) : "l"(a), "l"(b));
}

__device__ __forceinline__ float unpack_sum(unsigned long long p)
{
    float lo = __uint_as_float((unsigned int)(p & 0xffffffffu));
    float hi = __uint_as_float((unsigned int)(p >> 32));
    return lo + hi;
}

// ======================= lin1: h = relu(x @ W1^T + b1) =======================
// Warp layout: 16 k-lanes x 2 row-slots; each lane accumulates 4 full rows for
// its k. Inner product uses packed f32x2 FMAs (2 components per instruction).
__global__ void k_lin1(const float* __restrict__ x, const float* __restrict__ W1,
                       const float* __restrict__ b1, float* __restrict__ h, int N)
{
    __shared__ float4 Ws[H_DIM * 129];
    const int tid = threadIdx.x;
    const float4* W14 = (const float4*)W1;
    for (int i = tid; i < H_DIM * 128; i += blockDim.x) {
        int k = i >> 7, j = i & 127;
        Ws[k * 129 + j] = W14[k * 128 + j];
    }
    __syncthreads();

    const int warp = tid >> 5, lane = tid & 31;
    const int k = lane & 15, slot = lane >> 4;
    const int row0 = (blockIdx.x * 8 + warp) * 8 + slot * 4;

    const int r0 = min(row0 + 0, N - 1);
    const int r1 = min(row0 + 1, N - 1);
    const int r2 = min(row0 + 2, N - 1);
    const int r3 = min(row0 + 3, N - 1);

    const float4* x4 = (const float4*)x;
    const float4* p0 = x4 + (size_t)r0 * 128;
    const float4* p1 = x4 + (size_t)r1 * 128;
    const float4* p2 = x4 + (size_t)r2 * 128;
    const float4* p3 = x4 + (size_t)r3 * 128;

    unsigned long long a0l = 0ull, a0h = 0ull, a1l = 0ull, a1h = 0ull;
    unsigned long long a2l = 0ull, a2h = 0ull, a3l = 0ull, a3h = 0ull;

    #pragma unroll 4
    for (int j = 0; j < 128; j++) {
        const float4 w = Ws[k * 129 + j];
        const ulonglong2 ww = *reinterpret_cast<const ulonglong2*>(&w);
        float4 v; ulonglong2 vv;
        v = p0[j]; vv = *reinterpret_cast<const ulonglong2*>(&v);
        fma2(a0l, vv.x, ww.x); fma2(a0h, vv.y, ww.y);
        v = p1[j]; vv = *reinterpret_cast<const ulonglong2*>(&v);
        fma2(a1l, vv.x, ww.x); fma2(a1h, vv.y, ww.y);
        v = p2[j]; vv = *reinterpret_cast<const ulonglong2*>(&v);
        fma2(a2l, vv.x, ww.x); fma2(a2h, vv.y, ww.y);
        v = p3[j]; vv = *reinterpret_cast<const ulonglong2*>(&v);
        fma2(a3l, vv.x, ww.x); fma2(a3h, vv.y, ww.y);
    }
    const float bk = b1[k];
    const float v0 = fmaxf(unpack_sum(a0l) + unpack_sum(a0h) + bk, 0.f);
    const float v1 = fmaxf(unpack_sum(a1l) + unpack_sum(a1h) + bk, 0.f);
    const float v2 = fmaxf(unpack_sum(a2l) + unpack_sum(a2h) + bk, 0.f);
    const float v3 = fmaxf(unpack_sum(a3l) + unpack_sum(a3h) + bk, 0.f);

    if (row0 + 0 < N) h[(row0 + 0) * H_DIM + k] = v0;
    if (row0 + 1 < N) h[(row0 + 1) * H_DIM + k] = v1;
    if (row0 + 2 < N) h[(row0 + 2) * H_DIM + k] = v2;
    if (row0 + 3 < N) h[(row0 + 3) * H_DIM + k] = v3;
}

// ======================= CSR build (dst-grouped, incl. self-loops) ===========
__global__ void k_count_init(int N)
{
    int i = blockIdx.x * blockDim.x + threadIdx.x;
    if (i < N) g_counts[i] = 1;   // self-loop
}

__global__ void k_count(const int* __restrict__ ei, int E)
{
    int t = blockIdx.x * blockDim.x + threadIdx.x;
    int e = t * 4;
    if (e + 3 < E) {
        int4 d = *(const int4*)(ei + E + e);
        atomicAdd(&g_counts[d.x], 1);
        atomicAdd(&g_counts[d.y], 1);
        atomicAdd(&g_counts[d.z], 1);
        atomicAdd(&g_counts[d.w], 1);
    } else {
        for (int j = e; j < E; j++) atomicAdd(&g_counts[ei[E + j]], 1);
    }
}

// one block per chunk: tree-reduce 512 counts -> g_csums[chunk]
__global__ void k_csum(int N)
{
    const int c = blockIdx.x;
    const int tid = threadIdx.x;           // 256 threads
    const int i = c * CHUNK + tid;
    int s = 0;
    if (i < N) s = g_counts[i];
    if (i + 256 < N && tid + 256 < CHUNK) s += g_counts[i + 256];
    #pragma unroll
    for (int o = 16; o > 0; o >>= 1) s += __shfl_xor_sync(0xffffffffu, s, o);
    __shared__ int ws[8];
    if ((tid & 31) == 0) ws[tid >> 5] = s;
    __syncthreads();
    if (tid < 8) {
        int v = ws[tid];
        #pragma unroll
        for (int o = 4; o > 0; o >>= 1) v += __shfl_xor_sync(0x000000ffu, v, o);
        if (tid == 0) g_csums[c] = v;
    }
}

// single block exclusive scan over NC (<=256) chunk sums
__global__ void k_scan(int NC)
{
    const int tid = threadIdx.x;           // 256 threads
    const int lane = tid & 31, w = tid >> 5;
    int v = (tid < NC) ? g_csums[tid] : 0;
    int x = v;
    #pragma unroll
    for (int o = 1; o < 32; o <<= 1) {
        int t = __shfl_up_sync(0xffffffffu, x, o);
        if (lane >= o) x += t;
    }
    __shared__ int wsum[8];
    if (lane == 31) wsum[w] = x;
    __syncthreads();
    if (tid < 8) {
        int y = wsum[tid];
        #pragma unroll
        for (int o = 1; o < 8; o <<= 1) {
            int t = __shfl_up_sync(0x000000ffu, y, o);
            if (tid >= o) y += t;
        }
        wsum[tid] = y;
    }
    __syncthreads();
    const int incl = x + (w ? wsum[w - 1] : 0);
    if (tid < NC) g_csums[tid] = incl - v;   // exclusive
}

// one block (512 thr) per chunk: block-scan counts, add chunk base, emit offsets
__global__ void k_cscan(int N)
{
    const int c = blockIdx.x;
    const int tid = threadIdx.x;           // 512 threads
    const int i = c * CHUNK + tid;
    const int lane = tid & 31, w = tid >> 5;   // 16 warps
    const int v = (i < N) ? g_counts[i] : 0;
    int x = v;
    #pragma unroll
    for (int o = 1; o < 32; o <<= 1) {
        int t = __shfl_up_sync(0xffffffffu, x, o);
        if (lane >= o) x += t;
    }
    __shared__ int wsum[16];
    if (lane == 31) wsum[w] = x;
    __syncthreads();
    if (tid < 16) {
        int y = wsum[tid];
        #pragma unroll
        for (int o = 1; o < 16; o <<= 1) {
            int t = __shfl_up_sync(0x0000ffffu, y, o);
            if (tid >= o) y += t;
        }
        wsum[tid] = y;
    }
    __syncthreads();
    const int excl = x - v + (w ? wsum[w - 1] : 0);
    const int off = g_csums[c] + excl;
    if (i < N) {
        g_off[i] = off;
        g_cursor[i] = off;
        if (i == N - 1) g_off[N] = off + v;
    }
}

__global__ void k_scatter(const int* __restrict__ ei, int E, int N)
{
    int t = blockIdx.x * blockDim.x + threadIdx.x;
    if (t >= E + N) return;
    int s, d;
    if (t < E) { s = ei[t]; d = ei[E + t]; }
    else       { s = t - E; d = s; }
    int pos = atomicAdd(&g_cursor[d], 1);
    g_csr[pos] = s;
}

// ======================= fused AGNN layer (quad-cooperative) =================
// 4 lanes per dst node; all 4 lanes process the SAME edge together, each
// loading one float4 quarter of h[src] (one coalesced 64B gather per edge ->
// 1 L1 wavefront/edge instead of 4). Dot and src self-dot reduce in 2 quad
// shuffles each; src norm computed on the fly (no invn arrays at all).
// All 4 lanes carry identical (m, s); each owns 4 output components -> no
// final combine, direct float4 store per lane.
__global__ void k_agnn(const float* __restrict__ hin, float* __restrict__ hout,
                       const float* __restrict__ betap, int use_beta, int N)
{
    const int gid = blockIdx.x * blockDim.x + threadIdx.x;
    int node = gid >> 2;
    const int ql = gid & 3;
    const bool ok = (node < N);
    if (node >= N) node = N - 1;   // clamp: keep lanes alive for shuffles

    const float beta = use_beta ? betap[0] : 1.0f;
    const float4* __restrict__ h4 = (const float4*)hin;

    const float4 hd = h4[node * 4 + ql];

    // dst inverse norm via quad reduce of self-dot
    float sd = fmaf(hd.x, hd.x, fmaf(hd.y, hd.y, fmaf(hd.z, hd.z, hd.w * hd.w)));
    sd += __shfl_xor_sync(0xffffffffu, sd, 1);
    sd += __shfl_xor_sync(0xffffffffu, sd, 2);
    const float cd = beta * rsqrtf(fmaxf(sd, 1e-24f));

    const int beg = g_off[node], end = g_off[node + 1];

    float m = -1e30f, s = 0.f;
    float4 acc = make_float4(0.f, 0.f, 0.f, 0.f);

    int src = g_csr[beg];   // deg >= 1 always (self-loop)
    for (int i = beg; i < end; ) {
        const float4 hs = h4[src * 4 + ql];
        i++;
        if (i < end) src = g_csr[i];   // prefetch next index

        float pd = fmaf(hd.x, hs.x, fmaf(hd.y, hs.y, fmaf(hd.z, hs.z, hd.w * hs.w)));
        float ps = fmaf(hs.x, hs.x, fmaf(hs.y, hs.y, fmaf(hs.z, hs.z, hs.w * hs.w)));
        pd += __shfl_xor_sync(0xffffffffu, pd, 1);
        pd += __shfl_xor_sync(0xffffffffu, pd, 2);
        ps += __shfl_xor_sync(0xffffffffu, ps, 1);
        ps += __shfl_xor_sync(0xffffffffu, ps, 2);

        const float l  = cd * rsqrtf(fmaxf(ps, 1e-24f)) * pd;
        const float nm = fmaxf(m, l);
        const float sc = __expf(m - nm);
        const float w  = __expf(l - nm);
        s = fmaf(s, sc, w);
        acc.x = fmaf(acc.x, sc, w * hs.x);
        acc.y = fmaf(acc.y, sc, w * hs.y);
        acc.z = fmaf(acc.z, sc, w * hs.z);
        acc.w = fmaf(acc.w, sc, w * hs.w);
        m = nm;
    }

    if (ok) {
        const float is = 1.0f / s;
        ((float4*)hout)[node * 4 + ql] =
            make_float4(acc.x * is, acc.y * is, acc.z * is, acc.w * is);
    }
}

// ======================= classify + log_softmax ==============================
__global__ void k_out(const float* __restrict__ h, const float* __restrict__ W2,
                      const float* __restrict__ b2, float* __restrict__ out, int N)
{
    __shared__ float sW[C_OUT * H_DIM];
    __shared__ float sb[C_OUT];
    const int tid = threadIdx.x;
    if (tid < C_OUT * H_DIM) sW[tid] = W2[tid];
    if (tid < C_OUT) sb[tid] = b2[tid];
    __syncthreads();

    const int i = blockIdx.x * blockDim.x + tid;
    if (i >= N) return;

    float hv[16];
    const float4* h4 = (const float4*)h;
    #pragma unroll
    for (int t = 0; t < 4; t++) {
        float4 v = h4[i * 4 + t];
        hv[t * 4 + 0] = v.x; hv[t * 4 + 1] = v.y; hv[t * 4 + 2] = v.z; hv[t * 4 + 3] = v.w;
    }
    float lg[C_OUT];
    #pragma unroll
    for (int c = 0; c < C_OUT; c++) {
        float acc = sb[c];
        #pragma unroll
        for (int q = 0; q < 16; q++) acc = fmaf(hv[q], sW[c * 16 + q], acc);
        lg[c] = acc;
    }
    float mx = lg[0];
    #pragma unroll
    for (int c = 1; c < C_OUT; c++) mx = fmaxf(mx, lg[c]);
    float ssum = 0.f;
    #pragma unroll
    for (int c = 0; c < C_OUT; c++) ssum += __expf(lg[c] - mx);
    const float lse = mx + __logf(ssum);
    #pragma unroll
    for (int c = 0; c < C_OUT; c++) out[i * C_OUT + c] = lg[c] - lse;
}

// ======================= launch ==============================================
extern "C" void kernel_launch(void* const* d_in, const int* in_sizes, int n_in,
                              void* d_out, int out_size)
{
    const float* x     = (const float*)d_in[0];
    const int*   ei    = (const int*)d_in[1];
    const float* W1    = (const float*)d_in[2];
    const float* b1    = (const float*)d_in[3];
    const float* beta2 = (const float*)d_in[4];
    const float* beta3 = (const float*)d_in[5];
    const float* beta4 = (const float*)d_in[6];
    const float* W2    = (const float*)d_in[7];
    const float* b2    = (const float*)d_in[8];
    float* out = (float*)d_out;

    const int N = in_sizes[0] / F_IN;
    const int E = in_sizes[1] / 2;
    const int NC = (N + CHUNK - 1) / CHUNK;

    float *hA, *hB;
    cudaGetSymbolAddress((void**)&hA, g_h0);
    cudaGetSymbolAddress((void**)&hB, g_h1);

    // lin1
    k_lin1<<<(N + 63) / 64, 256>>>(x, W1, b1, hA, N);

    // CSR build
    k_count_init<<<(N + 255) / 256, 256>>>(N);
    k_count<<<((E + 3) / 4 + 255) / 256, 256>>>(ei, E);
    k_csum<<<NC, 256>>>(N);
    k_scan<<<1, 256>>>(NC);
    k_cscan<<<NC, 512>>>(N);
    k_scatter<<<(E + N + 255) / 256, 256>>>(ei, E, N);

    // 4 AGNN layers (layer 0: beta fixed at 1.0)
    const float* betas[4] = {nullptr, beta2, beta3, beta4};
    float* cur = hA; float* nxt = hB;
    for (int l = 0; l < 4; l++) {
        k_agnn<<<(N * 4 + 255) / 256, 256>>>(cur, nxt, betas[l], l > 0 ? 1 : 0, N);
        float* t = cur; cur = nxt; nxt = t;
    }

    // classify + log_softmax
    k_out<<<(N + 255) / 256, 256>>>(cur, W2, b2, out, N);
}

// round 9
// speedup vs baseline: 1.4254x; 1.4254x over previous
#include <cuda_runtime.h>

#define F_IN   512
#define H_DIM  16
#define C_OUT  7
#define NMAX   100000
#define EMAX   3200000
#define TOTMAX (NMAX + EMAX)
#define CHUNK  512
#define NCMAX  ((NMAX + CHUNK - 1) / CHUNK)

// -------- scratch (static device globals; no runtime allocation) --------
static __device__ float g_h0[NMAX * H_DIM];
static __device__ float g_h1[NMAX * H_DIM];
static __device__ float g_invnA[NMAX];
static __device__ float g_invnB[NMAX];
static __device__ int   g_counts[NMAX];
static __device__ int   g_cursor[NMAX];
static __device__ int   g_off[NMAX + 1];
static __device__ int   g_csr[TOTMAX];
static __device__ int   g_csums[NCMAX];

// packed f32x2 FMA: d = a*b + d (two fp32 lanes per instruction; PTX-only form)
__device__ __forceinline__ void fma2(unsigned long long& d,
                                     unsigned long long a, unsigned long long b)
{
    asm("fma.rn.f32x2 %0, %1, %2, %0;" : "+l"(d) : "l"(a), "l"(b));
}

__device__ __forceinline__ float unpack_sum(unsigned long long p)
{
    float lo = __uint_as_float((unsigned int)(p & 0xffffffffu));
    float hi = __uint_as_float((unsigned int)(p >> 32));
    return lo + hi;
}

// ======================= lin1: h = relu(x @ W1^T + b1), fused ||h|| ==========
// Warp layout: 16 k-lanes x 2 row-slots; each lane accumulates 4 full rows for
// its k via packed f32x2 FMAs. Butterfly across the 16 k-lanes produces the
// row sum-of-squares -> writes invn as well.
__global__ void k_lin1(const float* __restrict__ x, const float* __restrict__ W1,
                       const float* __restrict__ b1, float* __restrict__ h,
                       float* __restrict__ invn, int N)
{
    __shared__ float4 Ws[H_DIM * 129];
    const int tid = threadIdx.x;
    const float4* W14 = (const float4*)W1;
    for (int i = tid; i < H_DIM * 128; i += blockDim.x) {
        int k = i >> 7, j = i & 127;
        Ws[k * 129 + j] = W14[k * 128 + j];
    }
    __syncthreads();

    const int warp = tid >> 5, lane = tid & 31;
    const int k = lane & 15, slot = lane >> 4;
    const int row0 = (blockIdx.x * 8 + warp) * 8 + slot * 4;

    const int r0 = min(row0 + 0, N - 1);
    const int r1 = min(row0 + 1, N - 1);
    const int r2 = min(row0 + 2, N - 1);
    const int r3 = min(row0 + 3, N - 1);

    const float4* x4 = (const float4*)x;
    const float4* p0 = x4 + (size_t)r0 * 128;
    const float4* p1 = x4 + (size_t)r1 * 128;
    const float4* p2 = x4 + (size_t)r2 * 128;
    const float4* p3 = x4 + (size_t)r3 * 128;

    unsigned long long a0l = 0ull, a0h = 0ull, a1l = 0ull, a1h = 0ull;
    unsigned long long a2l = 0ull, a2h = 0ull, a3l = 0ull, a3h = 0ull;

    #pragma unroll 4
    for (int j = 0; j < 128; j++) {
        const float4 w = Ws[k * 129 + j];
        const ulonglong2 ww = *reinterpret_cast<const ulonglong2*>(&w);
        float4 v; ulonglong2 vv;
        v = p0[j]; vv = *reinterpret_cast<const ulonglong2*>(&v);
        fma2(a0l, vv.x, ww.x); fma2(a0h, vv.y, ww.y);
        v = p1[j]; vv = *reinterpret_cast<const ulonglong2*>(&v);
        fma2(a1l, vv.x, ww.x); fma2(a1h, vv.y, ww.y);
        v = p2[j]; vv = *reinterpret_cast<const ulonglong2*>(&v);
        fma2(a2l, vv.x, ww.x); fma2(a2h, vv.y, ww.y);
        v = p3[j]; vv = *reinterpret_cast<const ulonglong2*>(&v);
        fma2(a3l, vv.x, ww.x); fma2(a3h, vv.y, ww.y);
    }
    const float bk = b1[k];
    const float v0 = fmaxf(unpack_sum(a0l) + unpack_sum(a0h) + bk, 0.f);
    const float v1 = fmaxf(unpack_sum(a1l) + unpack_sum(a1h) + bk, 0.f);
    const float v2 = fmaxf(unpack_sum(a2l) + unpack_sum(a2h) + bk, 0.f);
    const float v3 = fmaxf(unpack_sum(a3l) + unpack_sum(a3h) + bk, 0.f);

    if (row0 + 0 < N) h[(row0 + 0) * H_DIM + k] = v0;
    if (row0 + 1 < N) h[(row0 + 1) * H_DIM + k] = v1;
    if (row0 + 2 < N) h[(row0 + 2) * H_DIM + k] = v2;
    if (row0 + 3 < N) h[(row0 + 3) * H_DIM + k] = v3;

    // sum of squares across the 16 k-lanes (xor offsets < 16 stay in-half)
    float s0 = v0 * v0, s1 = v1 * v1, s2 = v2 * v2, s3 = v3 * v3;
    #pragma unroll
    for (int o = 1; o < 16; o <<= 1) {
        s0 += __shfl_xor_sync(0xffffffffu, s0, o);
        s1 += __shfl_xor_sync(0xffffffffu, s1, o);
        s2 += __shfl_xor_sync(0xffffffffu, s2, o);
        s3 += __shfl_xor_sync(0xffffffffu, s3, o);
    }
    if (k == 0) {
        if (row0 + 0 < N) invn[row0 + 0] = 1.0f / fmaxf(sqrtf(s0), 1e-12f);
        if (row0 + 1 < N) invn[row0 + 1] = 1.0f / fmaxf(sqrtf(s1), 1e-12f);
        if (row0 + 2 < N) invn[row0 + 2] = 1.0f / fmaxf(sqrtf(s2), 1e-12f);
        if (row0 + 3 < N) invn[row0 + 3] = 1.0f / fmaxf(sqrtf(s3), 1e-12f);
    }
}

// ======================= CSR build (dst-grouped, incl. self-loops) ===========
__global__ void k_count_init(int N)
{
    int i = blockIdx.x * blockDim.x + threadIdx.x;
    if (i < N) g_counts[i] = 1;   // self-loop
}

__global__ void k_count(const int* __restrict__ ei, int E)
{
    int t = blockIdx.x * blockDim.x + threadIdx.x;
    int e = t * 4;
    if (e + 3 < E) {
        int4 d = *(const int4*)(ei + E + e);
        atomicAdd(&g_counts[d.x], 1);
        atomicAdd(&g_counts[d.y], 1);
        atomicAdd(&g_counts[d.z], 1);
        atomicAdd(&g_counts[d.w], 1);
    } else {
        for (int j = e; j < E; j++) atomicAdd(&g_counts[ei[E + j]], 1);
    }
}

// one block per chunk: tree-reduce 512 counts -> g_csums[chunk]
__global__ void k_csum(int N)
{
    const int c = blockIdx.x;
    const int tid = threadIdx.x;           // 256 threads
    const int i = c * CHUNK + tid;
    int s = 0;
    if (i < N) s = g_counts[i];
    if (i + 256 < N && tid + 256 < CHUNK) s += g_counts[i + 256];
    #pragma unroll
    for (int o = 16; o > 0; o >>= 1) s += __shfl_xor_sync(0xffffffffu, s, o);
    __shared__ int ws[8];
    if ((tid & 31) == 0) ws[tid >> 5] = s;
    __syncthreads();
    if (tid < 8) {
        int v = ws[tid];
        #pragma unroll
        for (int o = 4; o > 0; o >>= 1) v += __shfl_xor_sync(0x000000ffu, v, o);
        if (tid == 0) g_csums[c] = v;
    }
}

// single block exclusive scan over NC (<=256) chunk sums
__global__ void k_scan(int NC)
{
    const int tid = threadIdx.x;           // 256 threads
    const int lane = tid & 31, w = tid >> 5;
    int v = (tid < NC) ? g_csums[tid] : 0;
    int x = v;
    #pragma unroll
    for (int o = 1; o < 32; o <<= 1) {
        int t = __shfl_up_sync(0xffffffffu, x, o);
        if (lane >= o) x += t;
    }
    __shared__ int wsum[8];
    if (lane == 31) wsum[w] = x;
    __syncthreads();
    if (tid < 8) {
        int y = wsum[tid];
        #pragma unroll
        for (int o = 1; o < 8; o <<= 1) {
            int t = __shfl_up_sync(0x000000ffu, y, o);
            if (tid >= o) y += t;
        }
        wsum[tid] = y;
    }
    __syncthreads();
    const int incl = x + (w ? wsum[w - 1] : 0);
    if (tid < NC) g_csums[tid] = incl - v;   // exclusive
}

// one block (512 thr) per chunk: block-scan counts, add chunk base, emit offsets
__global__ void k_cscan(int N)
{
    const int c = blockIdx.x;
    const int tid = threadIdx.x;           // 512 threads
    const int i = c * CHUNK + tid;
    const int lane = tid & 31, w = tid >> 5;   // 16 warps
    const int v = (i < N) ? g_counts[i] : 0;
    int x = v;
    #pragma unroll
    for (int o = 1; o < 32; o <<= 1) {
        int t = __shfl_up_sync(0xffffffffu, x, o);
        if (lane >= o) x += t;
    }
    __shared__ int wsum[16];
    if (lane == 31) wsum[w] = x;
    __syncthreads();
    if (tid < 16) {
        int y = wsum[tid];
        #pragma unroll
        for (int o = 1; o < 16; o <<= 1) {
            int t = __shfl_up_sync(0x0000ffffu, y, o);
            if (tid >= o) y += t;
        }
        wsum[tid] = y;
    }
    __syncthreads();
    const int excl = x - v + (w ? wsum[w - 1] : 0);
    const int off = g_csums[c] + excl;
    if (i < N) {
        g_off[i] = off;
        g_cursor[i] = off;
        if (i == N - 1) g_off[N] = off + v;
    }
}

__global__ void k_scatter(const int* __restrict__ ei, int E, int N)
{
    int t = blockIdx.x * blockDim.x + threadIdx.x;
    if (t >= E + N) return;
    int s, d;
    if (t < E) { s = ei[t]; d = ei[E + t]; }
    else       { s = t - E; d = s; }
    int pos = atomicAdd(&g_cursor[d], 1);
    g_csr[pos] = s;
}

// ======================= fused AGNN layer (8-lane, no-max softmax) ===========
// Logits are beta * cosine similarity, so |l| <= |beta| (~1): expf cannot
// overflow and the online-max machinery is unnecessary. Each of 8 lanes per
// dst node accumulates plain (s, n[16]) with ONE expf per edge, no branches.
// Edge loop is software-pipelined: next csr index + invn load issue before
// the current row's math consumes its gather. Octet butterfly is a pure sum.
__global__ void k_agnn(const float* __restrict__ hin, float* __restrict__ hout,
                       const float* __restrict__ invn_in, float* __restrict__ invn_out,
                       const float* __restrict__ betap, int use_beta, int N)
{
    int gid = blockIdx.x * blockDim.x + threadIdx.x;
    int node = gid >> 3;
    int sub  = gid & 7;
    int store_ok = (node < N);
    if (node >= N) node = N - 1;   // clamp: keep all lanes alive for shuffles

    const float beta = use_beta ? betap[0] : 1.0f;
    const float4* __restrict__ h4 = (const float4*)hin;

    float hd[16];
    #pragma unroll
    for (int t = 0; t < 4; t++) {
        float4 v = h4[node * 4 + t];
        hd[t * 4 + 0] = v.x; hd[t * 4 + 1] = v.y; hd[t * 4 + 2] = v.z; hd[t * 4 + 3] = v.w;
    }
    const float cd = beta * invn_in[node];
    const int beg = g_off[node], end = g_off[node + 1];

    float s = 0.f;
    float n[16];
    #pragma unroll
    for (int q = 0; q < 16; q++) n[q] = 0.f;

    int i = beg + sub;
    if (i < end) {
        int   src = g_csr[i];
        float si  = invn_in[src];
        for (; i < end; ) {
            const int   csrc = src;
            const float csi  = si;
            float hs[16];
            #pragma unroll
            for (int t = 0; t < 4; t++) {
                float4 v = h4[csrc * 4 + t];
                hs[t * 4 + 0] = v.x; hs[t * 4 + 1] = v.y; hs[t * 4 + 2] = v.z; hs[t * 4 + 3] = v.w;
            }
            i += 8;
            if (i < end) {            // prefetch next edge's index + norm
                src = g_csr[i];
                si  = invn_in[src];
            }
            float dot = 0.f;
            #pragma unroll
            for (int q = 0; q < 16; q++) dot = fmaf(hd[q], hs[q], dot);
            const float w = __expf(cd * csi * dot);
            s += w;
            #pragma unroll
            for (int q = 0; q < 16; q++) n[q] = fmaf(w, hs[q], n[q]);
        }
    }

    // octet butterfly sum (warp-wide: serves 4 octets per instruction)
    #pragma unroll
    for (int o = 4; o > 0; o >>= 1) {
        s += __shfl_xor_sync(0xffffffffu, s, o);
        #pragma unroll
        for (int q = 0; q < 16; q++)
            n[q] += __shfl_xor_sync(0xffffffffu, n[q], o);
    }

    if (sub == 0 && store_ok) {
        const float is = 1.0f / s;
        float v[16];
        float ss = 0.f;
        #pragma unroll
        for (int q = 0; q < 16; q++) { v[q] = n[q] * is; ss = fmaf(v[q], v[q], ss); }
        float4* o4 = (float4*)hout;
        o4[node * 4 + 0] = make_float4(v[0],  v[1],  v[2],  v[3]);
        o4[node * 4 + 1] = make_float4(v[4],  v[5],  v[6],  v[7]);
        o4[node * 4 + 2] = make_float4(v[8],  v[9],  v[10], v[11]);
        o4[node * 4 + 3] = make_float4(v[12], v[13], v[14], v[15]);
        invn_out[node] = 1.0f / fmaxf(sqrtf(ss), 1e-12f);
    }
}

// ======================= classify + log_softmax ==============================
__global__ void k_out(const float* __restrict__ h, const float* __restrict__ W2,
                      const float* __restrict__ b2, float* __restrict__ out, int N)
{
    __shared__ float sW[C_OUT * H_DIM];
    __shared__ float sb[C_OUT];
    const int tid = threadIdx.x;
    if (tid < C_OUT * H_DIM) sW[tid] = W2[tid];
    if (tid < C_OUT) sb[tid] = b2[tid];
    __syncthreads();

    const int i = blockIdx.x * blockDim.x + tid;
    if (i >= N) return;

    float hv[16];
    const float4* h4 = (const float4*)h;
    #pragma unroll
    for (int t = 0; t < 4; t++) {
        float4 v = h4[i * 4 + t];
        hv[t * 4 + 0] = v.x; hv[t * 4 + 1] = v.y; hv[t * 4 + 2] = v.z; hv[t * 4 + 3] = v.w;
    }
    float lg[C_OUT];
    #pragma unroll
    for (int c = 0; c < C_OUT; c++) {
        float acc = sb[c];
        #pragma unroll
        for (int q = 0; q < 16; q++) acc = fmaf(hv[q], sW[c * 16 + q], acc);
        lg[c] = acc;
    }
    float mx = lg[0];
    #pragma unroll
    for (int c = 1; c < C_OUT; c++) mx = fmaxf(mx, lg[c]);
    float ssum = 0.f;
    #pragma unroll
    for (int c = 0; c < C_OUT; c++) ssum += __expf(lg[c] - mx);
    const float lse = mx + __logf(ssum);
    #pragma unroll
    for (int c = 0; c < C_OUT; c++) out[i * C_OUT + c] = lg[c] - lse;
}

// ======================= launch ==============================================
extern "C" void kernel_launch(void* const* d_in, const int* in_sizes, int n_in,
                              void* d_out, int out_size)
{
    const float* x     = (const float*)d_in[0];
    const int*   ei    = (const int*)d_in[1];
    const float* W1    = (const float*)d_in[2];
    const float* b1    = (const float*)d_in[3];
    const float* beta2 = (const float*)d_in[4];
    const float* beta3 = (const float*)d_in[5];
    const float* beta4 = (const float*)d_in[6];
    const float* W2    = (const float*)d_in[7];
    const float* b2    = (const float*)d_in[8];
    float* out = (float*)d_out;

    const int N = in_sizes[0] / F_IN;
    const int E = in_sizes[1] / 2;
    const int NC = (N + CHUNK - 1) / CHUNK;

    float *hA, *hB, *inA, *inB;
    cudaGetSymbolAddress((void**)&hA, g_h0);
    cudaGetSymbolAddress((void**)&hB, g_h1);
    cudaGetSymbolAddress((void**)&inA, g_invnA);
    cudaGetSymbolAddress((void**)&inB, g_invnB);

    // lin1 (+ invn of h)
    k_lin1<<<(N + 63) / 64, 256>>>(x, W1, b1, hA, inA, N);

    // CSR build
    k_count_init<<<(N + 255) / 256, 256>>>(N);
    k_count<<<((E + 3) / 4 + 255) / 256, 256>>>(ei, E);
    k_csum<<<NC, 256>>>(N);
    k_scan<<<1, 256>>>(NC);
    k_cscan<<<NC, 512>>>(N);
    k_scatter<<<(E + N + 255) / 256, 256>>>(ei, E, N);

    // 4 AGNN layers (layer 0: beta fixed at 1.0)
    const float* betas[4] = {nullptr, beta2, beta3, beta4};
    float* cur = hA; float* nxt = hB;
    float* icur = inA; float* inxt = inB;
    for (int l = 0; l < 4; l++) {
        k_agnn<<<(N * 8 + 255) / 256, 256>>>(cur, nxt, icur, inxt, betas[l], l > 0 ? 1 : 0, N);
        float* t = cur; cur = nxt; nxt = t;
        t = icur; icur = inxt; inxt = t;
    }

    // classify + log_softmax
    k_out<<<(N + 255) / 256, 256>>>(cur, W2, b2, out, N);
}

// round 10
// speedup vs baseline: 1.6883x; 1.1845x over previous
#include <cuda_runtime.h>

#define F_IN   512
#define H_DIM  16
#define C_OUT  7
#define NMAX   100000
#define EMAX   3200000
#define TOTMAX (NMAX + EMAX)
#define CHUNK  512
#define NCMAX  ((NMAX + CHUNK - 1) / CHUNK)

// -------- scratch (static device globals; no runtime allocation) --------
static __device__ float g_h0[NMAX * H_DIM];
static __device__ float g_h1[NMAX * H_DIM];
static __device__ float g_invnA[NMAX];
static __device__ float g_invnB[NMAX];
static __device__ int   g_counts[NMAX];
static __device__ int   g_cursor[NMAX];
static __device__ int   g_off[NMAX + 1];
static __device__ int   g_csr[TOTMAX];
static __device__ int   g_csums[NCMAX];

// packed f32x2 FMA: d = a*b + d (two fp32 lanes per instruction; PTX-only form)
__device__ __forceinline__ void fma2(unsigned long long& d,
                                     unsigned long long a, unsigned long long b)
{
    asm("fma.rn.f32x2 %0, %1, %2, %0;" : "+l"(d) : "l"(a), "l"(b));
}

__device__ __forceinline__ float unpack_sum(unsigned long long p)
{
    float lo = __uint_as_float((unsigned int)(p & 0xffffffffu));
    float hi = __uint_as_float((unsigned int)(p >> 32));
    return lo + hi;
}

// ======================= lin1: h = relu(x @ W1^T + b1), fused ||h|| ==========
__global__ void k_lin1(const float* __restrict__ x, const float* __restrict__ W1,
                       const float* __restrict__ b1, float* __restrict__ h,
                       float* __restrict__ invn, int N)
{
    __shared__ float4 Ws[H_DIM * 129];
    const int tid = threadIdx.x;
    const float4* W14 = (const float4*)W1;
    for (int i = tid; i < H_DIM * 128; i += blockDim.x) {
        int k = i >> 7, j = i & 127;
        Ws[k * 129 + j] = W14[k * 128 + j];
    }
    __syncthreads();

    const int warp = tid >> 5, lane = tid & 31;
    const int k = lane & 15, slot = lane >> 4;
    const int row0 = (blockIdx.x * 8 + warp) * 8 + slot * 4;

    const int r0 = min(row0 + 0, N - 1);
    const int r1 = min(row0 + 1, N - 1);
    const int r2 = min(row0 + 2, N - 1);
    const int r3 = min(row0 + 3, N - 1);

    const float4* x4 = (const float4*)x;
    const float4* p0 = x4 + (size_t)r0 * 128;
    const float4* p1 = x4 + (size_t)r1 * 128;
    const float4* p2 = x4 + (size_t)r2 * 128;
    const float4* p3 = x4 + (size_t)r3 * 128;

    unsigned long long a0l = 0ull, a0h = 0ull, a1l = 0ull, a1h = 0ull;
    unsigned long long a2l = 0ull, a2h = 0ull, a3l = 0ull, a3h = 0ull;

    #pragma unroll 4
    for (int j = 0; j < 128; j++) {
        const float4 w = Ws[k * 129 + j];
        const ulonglong2 ww = *reinterpret_cast<const ulonglong2*>(&w);
        float4 v; ulonglong2 vv;
        v = p0[j]; vv = *reinterpret_cast<const ulonglong2*>(&v);
        fma2(a0l, vv.x, ww.x); fma2(a0h, vv.y, ww.y);
        v = p1[j]; vv = *reinterpret_cast<const ulonglong2*>(&v);
        fma2(a1l, vv.x, ww.x); fma2(a1h, vv.y, ww.y);
        v = p2[j]; vv = *reinterpret_cast<const ulonglong2*>(&v);
        fma2(a2l, vv.x, ww.x); fma2(a2h, vv.y, ww.y);
        v = p3[j]; vv = *reinterpret_cast<const ulonglong2*>(&v);
        fma2(a3l, vv.x, ww.x); fma2(a3h, vv.y, ww.y);
    }
    const float bk = b1[k];
    const float v0 = fmaxf(unpack_sum(a0l) + unpack_sum(a0h) + bk, 0.f);
    const float v1 = fmaxf(unpack_sum(a1l) + unpack_sum(a1h) + bk, 0.f);
    const float v2 = fmaxf(unpack_sum(a2l) + unpack_sum(a2h) + bk, 0.f);
    const float v3 = fmaxf(unpack_sum(a3l) + unpack_sum(a3h) + bk, 0.f);

    if (row0 + 0 < N) h[(row0 + 0) * H_DIM + k] = v0;
    if (row0 + 1 < N) h[(row0 + 1) * H_DIM + k] = v1;
    if (row0 + 2 < N) h[(row0 + 2) * H_DIM + k] = v2;
    if (row0 + 3 < N) h[(row0 + 3) * H_DIM + k] = v3;

    float s0 = v0 * v0, s1 = v1 * v1, s2 = v2 * v2, s3 = v3 * v3;
    #pragma unroll
    for (int o = 1; o < 16; o <<= 1) {
        s0 += __shfl_xor_sync(0xffffffffu, s0, o);
        s1 += __shfl_xor_sync(0xffffffffu, s1, o);
        s2 += __shfl_xor_sync(0xffffffffu, s2, o);
        s3 += __shfl_xor_sync(0xffffffffu, s3, o);
    }
    if (k == 0) {
        if (row0 + 0 < N) invn[row0 + 0] = 1.0f / fmaxf(sqrtf(s0), 1e-12f);
        if (row0 + 1 < N) invn[row0 + 1] = 1.0f / fmaxf(sqrtf(s1), 1e-12f);
        if (row0 + 2 < N) invn[row0 + 2] = 1.0f / fmaxf(sqrtf(s2), 1e-12f);
        if (row0 + 3 < N) invn[row0 + 3] = 1.0f / fmaxf(sqrtf(s3), 1e-12f);
    }
}

// ======================= CSR build (dst-grouped, incl. self-loops) ===========
__global__ void k_count_init(int N)
{
    int i = blockIdx.x * blockDim.x + threadIdx.x;
    if (i < N) g_counts[i] = 1;   // self-loop
}

__global__ void k_count(const int* __restrict__ ei, int E)
{
    int t = blockIdx.x * blockDim.x + threadIdx.x;
    int e = t * 4;
    if (e + 3 < E) {
        int4 d = *(const int4*)(ei + E + e);
        atomicAdd(&g_counts[d.x], 1);
        atomicAdd(&g_counts[d.y], 1);
        atomicAdd(&g_counts[d.z], 1);
        atomicAdd(&g_counts[d.w], 1);
    } else {
        for (int j = e; j < E; j++) atomicAdd(&g_counts[ei[E + j]], 1);
    }
}

__global__ void k_csum(int N)
{
    const int c = blockIdx.x;
    const int tid = threadIdx.x;           // 256 threads
    const int i = c * CHUNK + tid;
    int s = 0;
    if (i < N) s = g_counts[i];
    if (i + 256 < N && tid + 256 < CHUNK) s += g_counts[i + 256];
    #pragma unroll
    for (int o = 16; o > 0; o >>= 1) s += __shfl_xor_sync(0xffffffffu, s, o);
    __shared__ int ws[8];
    if ((tid & 31) == 0) ws[tid >> 5] = s;
    __syncthreads();
    if (tid < 8) {
        int v = ws[tid];
        #pragma unroll
        for (int o = 4; o > 0; o >>= 1) v += __shfl_xor_sync(0x000000ffu, v, o);
        if (tid == 0) g_csums[c] = v;
    }
}

__global__ void k_scan(int NC)
{
    const int tid = threadIdx.x;           // 256 threads
    const int lane = tid & 31, w = tid >> 5;
    int v = (tid < NC) ? g_csums[tid] : 0;
    int x = v;
    #pragma unroll
    for (int o = 1; o < 32; o <<= 1) {
        int t = __shfl_up_sync(0xffffffffu, x, o);
        if (lane >= o) x += t;
    }
    __shared__ int wsum[8];
    if (lane == 31) wsum[w] = x;
    __syncthreads();
    if (tid < 8) {
        int y = wsum[tid];
        #pragma unroll
        for (int o = 1; o < 8; o <<= 1) {
            int t = __shfl_up_sync(0x000000ffu, y, o);
            if (tid >= o) y += t;
        }
        wsum[tid] = y;
    }
    __syncthreads();
    const int incl = x + (w ? wsum[w - 1] : 0);
    if (tid < NC) g_csums[tid] = incl - v;   // exclusive
}

__global__ void k_cscan(int N)
{
    const int c = blockIdx.x;
    const int tid = threadIdx.x;           // 512 threads
    const int i = c * CHUNK + tid;
    const int lane = tid & 31, w = tid >> 5;   // 16 warps
    const int v = (i < N) ? g_counts[i] : 0;
    int x = v;
    #pragma unroll
    for (int o = 1; o < 32; o <<= 1) {
        int t = __shfl_up_sync(0xffffffffu, x, o);
        if (lane >= o) x += t;
    }
    __shared__ int wsum[16];
    if (lane == 31) wsum[w] = x;
    __syncthreads();
    if (tid < 16) {
        int y = wsum[tid];
        #pragma unroll
        for (int o = 1; o < 16; o <<= 1) {
            int t = __shfl_up_sync(0x0000ffffu, y, o);
            if (tid >= o) y += t;
        }
        wsum[tid] = y;
    }
    __syncthreads();
    const int excl = x - v + (w ? wsum[w - 1] : 0);
    const int off = g_csums[c] + excl;
    if (i < N) {
        g_off[i] = off;
        g_cursor[i] = off;
        if (i == N - 1) g_off[N] = off + v;
    }
}

__global__ void k_scatter(const int* __restrict__ ei, int E, int N)
{
    int t = blockIdx.x * blockDim.x + threadIdx.x;
    if (t >= E + N) return;
    int s, d;
    if (t < E) { s = ei[t]; d = ei[E + t]; }
    else       { s = t - E; d = s; }
    int pos = atomicAdd(&g_cursor[d], 1);
    g_csr[pos] = s;
}

// ======================= fused AGNN layer (pair-cooperative gather) ==========
// 8 lanes per dst node = 4 edge-slots x 2 lanes. Both lanes of a pair handle
// the SAME edge; each loads HALF the 64B src row (2xLDG.128 = 32B) -> 2 L1
// wavefronts per edge instead of 4. The dot needs one pair-local shfl_xor(1).
// No softmax max (|logit| <= |beta|). Slot combine = xor{2,4} butterfly sum.
// Lanes of slot 0 store their half of the output row; for the LAST layer the
// pair computes the 7 logits + log_softmax directly (k_out fused away).
__global__ void k_agnn(const float* __restrict__ hin, float* __restrict__ hout,
                       const float* __restrict__ invn_in, float* __restrict__ invn_out,
                       const float* __restrict__ betap, int use_beta, int N,
                       int last, const float* __restrict__ W2,
                       const float* __restrict__ b2, float* __restrict__ out)
{
    const int gid = blockIdx.x * blockDim.x + threadIdx.x;
    int node = gid >> 3;
    const int o8   = gid & 7;        // position within octet
    const int slot = o8 >> 1;        // 0..3  edge slot
    const int p    = o8 & 1;         // 0..1  row half
    const unsigned pair_mask = 3u << ((threadIdx.x & 31) & ~1);
    const bool store_ok = (node < N);
    if (node >= N) node = N - 1;     // clamp: keep lanes alive for shuffles

    const float beta = use_beta ? betap[0] : 1.0f;
    const float4* __restrict__ h4 = (const float4*)hin;

    // this lane's half of the dst row
    float hd[8];
    {
        float4 a = h4[node * 4 + p * 2 + 0];
        float4 b = h4[node * 4 + p * 2 + 1];
        hd[0] = a.x; hd[1] = a.y; hd[2] = a.z; hd[3] = a.w;
        hd[4] = b.x; hd[5] = b.y; hd[6] = b.z; hd[7] = b.w;
    }
    const float cd = beta * invn_in[node];
    const int beg = g_off[node], end = g_off[node + 1];

    float s = 0.f;
    float n[8];
    #pragma unroll
    for (int q = 0; q < 8; q++) n[q] = 0.f;

    int i = beg + slot;
    if (i < end) {
        int   src = g_csr[i];
        float si  = invn_in[src];
        while (i < end) {
            const int   csrc = src;
            const float csi  = si;
            float4 a = h4[csrc * 4 + p * 2 + 0];
            float4 b = h4[csrc * 4 + p * 2 + 1];
            i += 4;
            if (i < end) {           // prefetch next edge's index + norm
                src = g_csr[i];
                si  = invn_in[src];
            }
            float hs[8];
            hs[0] = a.x; hs[1] = a.y; hs[2] = a.z; hs[3] = a.w;
            hs[4] = b.x; hs[5] = b.y; hs[6] = b.z; hs[7] = b.w;
            float pd = 0.f;
            #pragma unroll
            for (int q = 0; q < 8; q++) pd = fmaf(hd[q], hs[q], pd);
            pd += __shfl_xor_sync(pair_mask, pd, 1);    // full 16-dot on both lanes
            const float w = __expf(cd * csi * pd);
            s += w;
            #pragma unroll
            for (int q = 0; q < 8; q++) n[q] = fmaf(w, hs[q], n[q]);
        }
    }

    // combine across the 4 slots (preserves half p); s becomes the full sum
    #pragma unroll
    for (int o = 2; o <= 4; o <<= 1) {
        s += __shfl_xor_sync(0xffffffffu, s, o);
        #pragma unroll
        for (int q = 0; q < 8; q++)
            n[q] += __shfl_xor_sync(0xffffffffu, n[q], o);
    }

    if (slot == 0) {   // lanes o8==0 (half 0) and o8==1 (half 1)
        const float is = 1.0f / s;
        float v[8];
        float ss = 0.f;
        #pragma unroll
        for (int q = 0; q < 8; q++) { v[q] = n[q] * is; ss = fmaf(v[q], v[q], ss); }

        if (!last) {
            if (store_ok) {
                float4* o4 = (float4*)hout;
                o4[node * 4 + p * 2 + 0] = make_float4(v[0], v[1], v[2], v[3]);
                o4[node * 4 + p * 2 + 1] = make_float4(v[4], v[5], v[6], v[7]);
            }
            ss += __shfl_xor_sync(pair_mask, ss, 1);
            if (p == 0 && store_ok)
                invn_out[node] = 1.0f / fmaxf(sqrtf(ss), 1e-12f);
        } else {
            // fused classify + log_softmax: partial logits over this half
            float lg[C_OUT];
            #pragma unroll
            for (int c = 0; c < C_OUT; c++) {
                float acc = 0.f;
                #pragma unroll
                for (int q = 0; q < 8; q++)
                    acc = fmaf(v[q], W2[c * H_DIM + p * 8 + q], acc);
                lg[c] = acc;
            }
            #pragma unroll
            for (int c = 0; c < C_OUT; c++)
                lg[c] += __shfl_xor_sync(pair_mask, lg[c], 1);
            if (p == 0 && store_ok) {
                #pragma unroll
                for (int c = 0; c < C_OUT; c++) lg[c] += b2[c];
                float mx = lg[0];
                #pragma unroll
                for (int c = 1; c < C_OUT; c++) mx = fmaxf(mx, lg[c]);
                float ssum = 0.f;
                #pragma unroll
                for (int c = 0; c < C_OUT; c++) ssum += __expf(lg[c] - mx);
                const float lse = mx + __logf(ssum);
                #pragma unroll
                for (int c = 0; c < C_OUT; c++) out[node * C_OUT + c] = lg[c] - lse;
            }
        }
    }
}

// ======================= launch ==============================================
extern "C" void kernel_launch(void* const* d_in, const int* in_sizes, int n_in,
                              void* d_out, int out_size)
{
    const float* x     = (const float*)d_in[0];
    const int*   ei    = (const int*)d_in[1];
    const float* W1    = (const float*)d_in[2];
    const float* b1    = (const float*)d_in[3];
    const float* beta2 = (const float*)d_in[4];
    const float* beta3 = (const float*)d_in[5];
    const float* beta4 = (const float*)d_in[6];
    const float* W2    = (const float*)d_in[7];
    const float* b2    = (const float*)d_in[8];
    float* out = (float*)d_out;

    const int N = in_sizes[0] / F_IN;
    const int E = in_sizes[1] / 2;
    const int NC = (N + CHUNK - 1) / CHUNK;

    float *hA, *hB, *inA, *inB;
    cudaGetSymbolAddress((void**)&hA, g_h0);
    cudaGetSymbolAddress((void**)&hB, g_h1);
    cudaGetSymbolAddress((void**)&inA, g_invnA);
    cudaGetSymbolAddress((void**)&inB, g_invnB);

    // lin1 (+ invn of h)
    k_lin1<<<(N + 63) / 64, 256>>>(x, W1, b1, hA, inA, N);

    // CSR build
    k_count_init<<<(N + 255) / 256, 256>>>(N);
    k_count<<<((E + 3) / 4 + 255) / 256, 256>>>(ei, E);
    k_csum<<<NC, 256>>>(N);
    k_scan<<<1, 256>>>(NC);
    k_cscan<<<NC, 512>>>(N);
    k_scatter<<<(E + N + 255) / 256, 256>>>(ei, E, N);

    // 4 AGNN layers (layer 0: beta fixed at 1.0; layer 3 fuses classify)
    const float* betas[4] = {nullptr, beta2, beta3, beta4};
    float* cur = hA; float* nxt = hB;
    float* icur = inA; float* inxt = inB;
    for (int l = 0; l < 4; l++) {
        const int last = (l == 3);
        k_agnn<<<(N * 8 + 255) / 256, 256>>>(cur, nxt, icur, inxt,
                                             betas[l], l > 0 ? 1 : 0, N,
                                             last, W2, b2, out);
        float* t = cur; cur = nxt; nxt = t;
        t = icur; icur = inxt; inxt = t;
    }
}